// round 1
// baseline (speedup 1.0000x reference)
#include <cuda_runtime.h>

// Problem constants
#define NB     4
#define SL     2048
#define NHEADS 8
#define HD     64
#define FEA    512
#define NHTOT  32          // NB * NHEADS

typedef unsigned long long u64;

// ---------------------------------------------------------------------------
// Scratch (device globals — allocation-free rule)
// ---------------------------------------------------------------------------
__device__ float g_q[NHTOT * SL * HD];     // [nh][l][d], 16.8 MB
__device__ float g_k[NHTOT * SL * HD];
__device__ float g_v[NHTOT * SL * HD];
__device__ float g_attn[NB * SL * FEA];    // [n][l][h*64+j]

// ---------------------------------------------------------------------------
// Packed fp32x2 helpers (Blackwell FFMA2 — only reachable via PTX)
// ---------------------------------------------------------------------------
__device__ __forceinline__ u64 fma2(u64 a, u64 b, u64 c) {
    u64 d;
    asm("fma.rn.f32x2 %0, %1, %2, %3;" : "=l"(d) : "l"(a), "l"(b), "l"(c));
    return d;
}
__device__ __forceinline__ u64 pack2(float lo, float hi) {
    u64 r;
    asm("mov.b64 %0, {%1, %2};" : "=l"(r) : "f"(lo), "f"(hi));
    return r;
}
__device__ __forceinline__ float2 unpack2(u64 v) {
    float2 f;
    asm("mov.b64 {%0, %1}, %2;" : "=f"(f.x), "=f"(f.y) : "l"(v));
    return f;
}

// ---------------------------------------------------------------------------
// Kernel 1: per-head projections q/k/v = x_head @ W{q,k,v}
// grid (16, 32) = (l-tile of 128, nh), block 128 (thread = one l row)
// ---------------------------------------------------------------------------
__global__ void __launch_bounds__(128, 3)
proj_kernel(const float* __restrict__ x,
            const float* __restrict__ Wq,
            const float* __restrict__ Wk,
            const float* __restrict__ Wv)
{
    __shared__ __align__(16) float ws[3][64 * 64];   // 48 KB

    const int nh = blockIdx.y;
    const int n  = nh >> 3;
    const int h  = nh & 7;
    const int l  = blockIdx.x * 128 + threadIdx.x;

    const float* wsrc[3] = {Wq, Wk, Wv};
    #pragma unroll
    for (int m = 0; m < 3; m++)
        for (int i = threadIdx.x; i < 1024; i += 128)
            ((float4*)ws[m])[i] = ((const float4*)wsrc[m])[i];
    __syncthreads();

    // x row (64 floats) into registers
    float xr[64];
    const float4* xp = (const float4*)(x + ((size_t)n * SL + l) * FEA + h * HD);
    #pragma unroll
    for (int i = 0; i < 16; i++) {
        float4 t = xp[i];
        xr[4*i+0] = t.x; xr[4*i+1] = t.y; xr[4*i+2] = t.z; xr[4*i+3] = t.w;
    }

    const size_t off = ((size_t)nh * SL + l) * HD;
    float* dst[3] = {g_q + off, g_k + off, g_v + off};

    #pragma unroll
    for (int m = 0; m < 3; m++) {
        u64 acc[32];
        #pragma unroll
        for (int i = 0; i < 32; i++) acc[i] = 0ull;

        #pragma unroll 4
        for (int d = 0; d < 64; d++) {
            u64 xd = pack2(xr[d], xr[d]);
            const ulonglong2* wr = (const ulonglong2*)&ws[m][d * 64];  // broadcast
            #pragma unroll
            for (int p = 0; p < 16; p++) {
                ulonglong2 w = wr[p];
                acc[2*p+0] = fma2(xd, w.x, acc[2*p+0]);
                acc[2*p+1] = fma2(xd, w.y, acc[2*p+1]);
            }
        }
        float4* op = (float4*)dst[m];
        #pragma unroll
        for (int i = 0; i < 16; i++) {
            float2 a = unpack2(acc[2*i+0]);
            float2 b = unpack2(acc[2*i+1]);
            op[i] = make_float4(a.x, a.y, b.x, b.y);
        }
    }
}

// ---------------------------------------------------------------------------
// Kernel 2: fused attention  O = relu(Q K^T)^2 V  per (n,h)
// grid (16, 32) = (q-tile of 128, nh), block 128 (thread = one q row)
// ---------------------------------------------------------------------------
__global__ void __launch_bounds__(128, 3)
attn_kernel()
{
    __shared__ __align__(16) float Ksh[64 * HD];   // 16 KB (64-key chunk)
    __shared__ __align__(16) float Vsh[64 * HD];   // 16 KB

    const int nh  = blockIdx.y;
    const int row = blockIdx.x * 128 + threadIdx.x;

    // q row -> 32 packed regs
    u64 q2[32];
    {
        const ulonglong2* qp = (const ulonglong2*)(g_q + ((size_t)nh * SL + row) * HD);
        #pragma unroll
        for (int i = 0; i < 16; i++) {
            ulonglong2 t = qp[i];
            q2[2*i+0] = t.x;
            q2[2*i+1] = t.y;
        }
    }

    u64 o2[32];
    #pragma unroll
    for (int i = 0; i < 32; i++) o2[i] = 0ull;

    const float4* kbase = (const float4*)(g_k + (size_t)nh * SL * HD);
    const float4* vbase = (const float4*)(g_v + (size_t)nh * SL * HD);

    for (int kb = 0; kb < SL / 64; kb++) {
        __syncthreads();
        const float4* ks = kbase + kb * (64 * HD / 4);
        const float4* vs = vbase + kb * (64 * HD / 4);
        #pragma unroll
        for (int i = 0; i < 8; i++) {
            ((float4*)Ksh)[threadIdx.x + i * 128] = ks[threadIdx.x + i * 128];
            ((float4*)Vsh)[threadIdx.x + i * 128] = vs[threadIdx.x + i * 128];
        }
        __syncthreads();

        #pragma unroll 2
        for (int l = 0; l < 64; l++) {
            // dot(q, k_l): two independent packed chains (lat 4 / rt 2)
            const ulonglong2* kr = (const ulonglong2*)(Ksh + l * HD);  // broadcast
            u64 sa = 0ull, sb = 0ull;
            #pragma unroll
            for (int i = 0; i < 16; i++) {
                ulonglong2 kk = kr[i];
                sa = fma2(q2[2*i+0], kk.x, sa);
                sb = fma2(q2[2*i+1], kk.y, sb);
            }
            float2 fa = unpack2(sa);
            float2 fb = unpack2(sb);
            float s = (fa.x + fa.y) + (fb.x + fb.y);
            s = fmaxf(s, 0.0f);
            float p = s * s;
            u64 p2 = pack2(p, p);

            // O += p * v_l  (rank-1 update, broadcast V row)
            const ulonglong2* vr = (const ulonglong2*)(Vsh + l * HD);
            #pragma unroll
            for (int i = 0; i < 16; i++) {
                ulonglong2 vv = vr[i];
                o2[2*i+0] = fma2(p2, vv.x, o2[2*i+0]);
                o2[2*i+1] = fma2(p2, vv.y, o2[2*i+1]);
            }
        }
    }

    // write O row into x-layout scratch [n][row][h*64 + j]
    const int n = nh >> 3, h = nh & 7;
    float4* op = (float4*)(g_attn + ((size_t)n * SL + row) * FEA + h * HD);
    #pragma unroll
    for (int i = 0; i < 16; i++) {
        float2 a = unpack2(o2[2*i+0]);
        float2 b = unpack2(o2[2*i+1]);
        op[i] = make_float4(a.x, a.y, b.x, b.y);
    }
}

// ---------------------------------------------------------------------------
// Kernel 3: out = g_attn[8192,512] @ Wo[512,64] + bo
// grid 128 (64-row tiles), block 256 (16x16, 4x4 frag per thread)
// ---------------------------------------------------------------------------
__global__ void __launch_bounds__(256)
out_kernel(const float* __restrict__ Wo,
           const float* __restrict__ bo,
           float* __restrict__ out)
{
    __shared__ __align__(16) float xs[64][68];   // [row][k], padded
    __shared__ __align__(16) float wsh[64][64];  // [k][c]

    const int row0 = blockIdx.x * 64;
    const int tid  = threadIdx.x;
    const int ty   = tid >> 4, tx = tid & 15;
    const int r0   = ty * 4,  c0 = tx * 4;

    u64 acc[4][2];
    #pragma unroll
    for (int i = 0; i < 4; i++) { acc[i][0] = 0ull; acc[i][1] = 0ull; }

    for (int kc = 0; kc < FEA; kc += 64) {
        __syncthreads();
        #pragma unroll
        for (int j = 0; j < 4; j++) {
            int f  = tid + j * 256;
            int r  = f >> 4;
            int k4 = (f & 15) * 4;
            float4 xv = *(const float4*)(g_attn + ((size_t)(row0 + r)) * FEA + kc + k4);
            *(float4*)&xs[r][k4] = xv;
            float4 wv = *(const float4*)(Wo + (size_t)(kc + r) * HD + k4);
            *(float4*)&wsh[r][k4] = wv;
        }
        __syncthreads();

        #pragma unroll 8
        for (int k = 0; k < 64; k++) {
            ulonglong2 wv = *(const ulonglong2*)&wsh[k][c0];
            #pragma unroll
            for (int i = 0; i < 4; i++) {
                float xv = xs[r0 + i][k];        // broadcast within half-warp
                u64 x2 = pack2(xv, xv);
                acc[i][0] = fma2(x2, wv.x, acc[i][0]);
                acc[i][1] = fma2(x2, wv.y, acc[i][1]);
            }
        }
    }

    float4 bv = *(const float4*)(bo + c0);
    #pragma unroll
    for (int i = 0; i < 4; i++) {
        float2 a = unpack2(acc[i][0]);
        float2 b = unpack2(acc[i][1]);
        float4 o = make_float4(a.x + bv.x, a.y + bv.y, b.x + bv.z, b.y + bv.w);
        *(float4*)(out + (size_t)(row0 + r0 + i) * HD + c0) = o;
    }
}

// ---------------------------------------------------------------------------
// Entry point
// ---------------------------------------------------------------------------
extern "C" void kernel_launch(void* const* d_in, const int* in_sizes, int n_in,
                              void* d_out, int out_size)
{
    const float* query = (const float*)d_in[0];
    const float* Wv    = (const float*)d_in[1];
    const float* Wk    = (const float*)d_in[2];
    const float* Wq    = (const float*)d_in[3];
    const float* Wo    = (const float*)d_in[4];
    const float* bo    = (const float*)d_in[5];
    float* out = (float*)d_out;

    proj_kernel<<<dim3(16, 32), 128>>>(query, Wq, Wk, Wv);
    attn_kernel<<<dim3(16, 32), 128>>>();
    out_kernel<<<128, 256>>>(Wo, bo, out);
}